// round 14
// baseline (speedup 1.0000x reference)
#include <cuda_runtime.h>
#include <cstdint>

#define LL 4096
#define CC 32
#define LT 16           // l per CTA; warp w owns l = l0 + w
#define THREADS 512     // 16 warps
#define BCH 16          // b rows per chunk (one m16 tile)
#define NCH 4           // chunks per CTA (64 b)
#define BSPLIT 2        // b halves across CTAs

#define XS_U32 (LT * 512)        // 16 l-planes x (16 b x 32 slots) = 32 KB
#define OPITCH 20                // 2*20 == 8 mod 32 -> conflict-free compute STS
#define OPLANE 642               // == 2 mod 32 -> conflict-free out gather
#define OS_FLOATS (LT * OPLANE)
#define SMEM_BYTES (XS_U32 * 4 + OS_FLOATS * 4)   // 73856 B -> 2 CTAs/SM

__device__ __forceinline__ uint32_t f2tf32(float f) {
    uint32_t r;
    asm("cvt.rna.tf32.f32 %0, %1;" : "=r"(r) : "f"(f));
    return r;
}

__device__ __forceinline__ void mma_tf32(
    float& d0, float& d1, float& d2, float& d3,
    uint32_t a0, uint32_t a1, uint32_t a2, uint32_t a3,
    uint32_t b0, uint32_t b1,
    float c0, float c1, float c2, float c3) {
    asm("mma.sync.aligned.m16n8k8.row.col.f32.tf32.tf32.f32 "
        "{%0,%1,%2,%3}, {%4,%5,%6,%7}, {%8,%9}, {%10,%11,%12,%13};"
        : "=f"(d0), "=f"(d1), "=f"(d2), "=f"(d3)
        : "r"(a0), "r"(a1), "r"(a2), "r"(a3), "r"(b0), "r"(b1),
          "f"(c0), "f"(c1), "f"(c2), "f"(c3));
}

__global__ void __launch_bounds__(THREADS, 2)
dyna_dec_kernel(const float* __restrict__ x, const float* __restrict__ weight,
                const float* __restrict__ bias, float* __restrict__ out) {
    extern __shared__ __align__(16) char smem[];
    uint32_t* x_s = (uint32_t*)smem;
    float*    o_s = (float*)(smem + XS_U32 * 4);

    const int tid  = threadIdx.x;
    const int w    = tid >> 5;       // warp = local l (0..15)
    const int lane = tid & 31;
    const int q    = lane & 3;       // mma k-in-tile
    const int p    = lane >> 2;      // mma row/col group
    const int b0   = blockIdx.x * (BCH * NCH);   // b-split fastest: weight L2 reuse
    const int l0   = blockIdx.y * LT;
    const int lg   = l0 + w;

    // ---- B fragments (32 regs) + bias (8 regs) for this warp's l ----
    uint32_t bf[4][4][2];
    float    bb[4][2];
    {
        const float* wp = weight + (size_t)lg * CC * CC;
        #pragma unroll
        for (int nt = 0; nt < 4; nt++) {
            #pragma unroll
            for (int kt = 0; kt < 4; kt++) {
                bf[kt][nt][0] = f2tf32(__ldg(wp + (8 * kt + q) * CC + 8 * nt + p));
                bf[kt][nt][1] = f2tf32(__ldg(wp + (8 * kt + q + 4) * CC + 8 * nt + p));
            }
            float2 bv = *(const float2*)(bias + (size_t)lg * CC + 8 * nt + 2 * q);
            bb[nt][0] = bv.x;
            bb[nt][1] = bv.y;
        }
    }

    for (int ch = 0; ch < NCH; ch++) {
        const int cb = b0 + ch * BCH;

        // ---- stage: 8 rows x 64B per instr (8 lines); conflict-free STS ----
        #pragma unroll
        for (int it = 0; it < 4; it++) {
            int combo = it * 16 + w;             // 0..63
            int bl = combo >> 2, qq = combo & 3;
            int cc = lane >> 2, s = lane & 3;
            int c  = 4 * cc + qq;
            float4 v = *(const float4*)(x + ((size_t)((cb + bl) * CC + c)) * LL + l0 + 4 * s);
            int slot = (8 * qq + cc + 4 * (bl & 7) + 8 * s) & 31;  // banks cc+8s: distinct
            uint32_t* dst = x_s + (4 * s) * 512 + bl * 32 + slot;
            dst[0]    = f2tf32(v.x);
            dst[512]  = f2tf32(v.y);
            dst[1024] = f2tf32(v.z);
            dst[1536] = f2tf32(v.w);
        }
        __syncthreads();   // x_s ready; also fences out-pass(ch-1) o_s reads

        // ---- compute: warp w -> l = w; 4x LDS.128 + 16 mma; acc scoped per nt ----
        {
            const uint32_t* xp = x_s + w * 512;
            const int rotc = 8 * (w >> 2);
            const int o1 = (8 * q + 4 * p + rotc) & 31;      // mult of 4 -> no row wrap
            const int o2 = (8 * q + 4 * p + 4 + rotc) & 31;
            uint4 v00 = *(const uint4*)(xp + p * 32 + o1);
            uint4 v01 = *(const uint4*)(xp + p * 32 + o2);
            uint4 v10 = *(const uint4*)(xp + (p + 8) * 32 + o1);
            uint4 v11 = *(const uint4*)(xp + (p + 8) * 32 + o2);

            float* op = o_s + w * OPLANE;
            #pragma unroll
            for (int nt = 0; nt < 4; nt++) {
                float a0 = bb[nt][0], a1 = bb[nt][1];
                float a2 = bb[nt][0], a3 = bb[nt][1];
                mma_tf32(a0, a1, a2, a3, v00.x, v10.x, v00.y, v10.y,
                         bf[0][nt][0], bf[0][nt][1], a0, a1, a2, a3);
                mma_tf32(a0, a1, a2, a3, v00.z, v10.z, v00.w, v10.w,
                         bf[1][nt][0], bf[1][nt][1], a0, a1, a2, a3);
                mma_tf32(a0, a1, a2, a3, v01.x, v11.x, v01.y, v11.y,
                         bf[2][nt][0], bf[2][nt][1], a0, a1, a2, a3);
                mma_tf32(a0, a1, a2, a3, v01.z, v11.z, v01.w, v11.w,
                         bf[3][nt][0], bf[3][nt][1], a0, a1, a2, a3);
                // o_s[l][d*20 + b]; banks 8q+p (+20): conflict-free
                int d = 8 * nt + 2 * q;
                op[d * OPITCH + p]           = a0;
                op[(d + 1) * OPITCH + p]     = a1;
                op[d * OPITCH + p + 8]       = a2;
                op[(d + 1) * OPITCH + p + 8] = a3;
            }
        }
        __syncthreads();   // o_s ready

        // ---- out-pass: d fixed per instr, 8 b-rows x 64B (8 lines/STG) ----
        #pragma unroll
        for (int it = 0; it < 4; it++) {
            int combo = it * 16 + w;             // 0..63
            int d = combo >> 1, bh = combo & 1;
            int blx = lane & 7, s2 = lane >> 3;
            int bl = bh * 8 + blx;
            const float* src = o_s + (4 * s2) * OPLANE + d * OPITCH + bl;
            float4 v;                            // banks 8s2+blx: conflict-free
            v.x = src[0 * OPLANE];
            v.y = src[1 * OPLANE];
            v.z = src[2 * OPLANE];
            v.w = src[3 * OPLANE];
            *(float4*)(out + ((size_t)((cb + bl) * CC + d)) * LL + l0 + 4 * s2) = v;
        }
        // next stage writes x_s only (disjoint from o_s); next compute's o_s
        // writes are fenced by the next stage-end sync.
    }
}

extern "C" void kernel_launch(void* const* d_in, const int* in_sizes, int n_in,
                              void* d_out, int out_size) {
    const float* x      = (const float*)d_in[0];
    // d_in[1] = px, unused by the reference
    const float* weight = (const float*)d_in[2];
    const float* bias   = (const float*)d_in[3];
    float* out          = (float*)d_out;

    cudaFuncSetAttribute(dyna_dec_kernel, cudaFuncAttributeMaxDynamicSharedMemorySize,
                         SMEM_BYTES);
    dim3 grid(BSPLIT, LL / LT);   // (2, 256): weight-sharing siblings adjacent
    dim3 block(THREADS);
    dyna_dec_kernel<<<grid, block, SMEM_BYTES>>>(x, weight, bias, out);
}

// round 16
// speedup vs baseline: 1.0979x; 1.0979x over previous
#include <cuda_runtime.h>
#include <cstdint>

#define LL 4096
#define CC 32
#define LT 8            // l per CTA; warp w owns l = l0 + w
#define THREADS 256     // 8 warps
#define BCH 16          // b rows per chunk (one m16 tile)
#define NCH 4           // chunks per CTA (64 b)
#define BSPLIT 2        // b halves across CTAs

#define XPLANE 512      // l-plane stride (16B-aligned); s-shift lives in slot index
#define OPITCH 20       // banks 8q+p at compute store: conflict-free
#define OPLANE 644      // ==4 mod 32: gather banks bl+16s2+4j: conflict-free

__device__ __forceinline__ uint32_t f2tf32(float f) {
    uint32_t r;
    asm("cvt.rna.tf32.f32 %0, %1;" : "=r"(r) : "f"(f));
    return r;
}

__device__ __forceinline__ void mma_tf32(
    float& d0, float& d1, float& d2, float& d3,
    uint32_t a0, uint32_t a1, uint32_t a2, uint32_t a3,
    uint32_t b0, uint32_t b1,
    float c0, float c1, float c2, float c3) {
    asm("mma.sync.aligned.m16n8k8.row.col.f32.tf32.tf32.f32 "
        "{%0,%1,%2,%3}, {%4,%5,%6,%7}, {%8,%9}, {%10,%11,%12,%13};"
        : "=f"(d0), "=f"(d1), "=f"(d2), "=f"(d3)
        : "r"(a0), "r"(a1), "r"(a2), "r"(a3), "r"(b0), "r"(b1),
          "f"(c0), "f"(c1), "f"(c2), "f"(c3));
}

__global__ void __launch_bounds__(THREADS, 3)
dyna_dec_kernel(const float* __restrict__ x, const float* __restrict__ weight,
                const float* __restrict__ bias, float* __restrict__ out) {
    __shared__ __align__(16) uint32_t x_s[LT * XPLANE];   // 8 l-planes x (16b x 32 slots)
    __shared__ __align__(16) float    o_s[LT * OPLANE];
    __shared__ __align__(16) float    bias_s[LT * CC];

    const int tid  = threadIdx.x;
    const int w    = tid >> 5;       // warp = local l
    const int lane = tid & 31;
    const int q    = lane & 3;       // mma k-in-tile
    const int p    = lane >> 2;      // mma row/col group
    const int b0   = blockIdx.x * (BCH * NCH);   // b-split fastest: weight L2 reuse
    const int l0   = blockIdx.y * LT;
    const int lg   = l0 + w;

    // ---------- prologue: issue chunk-0 prefetch FIRST ----------
    float4 pf[4];
    #pragma unroll
    for (int it = 0; it < 4; it++) {
        int i = it * THREADS + tid;
        int s = i & 1, r = i >> 1;
        pf[it] = *(const float4*)(x + ((size_t)((b0 + (r >> 5)) * CC + (r & 31))) * LL + l0 + 4 * s);
    }
    // bias -> smem (one-time)
    if (tid < 64)
        *(float4*)(bias_s + tid * 4) = *(const float4*)(bias + (size_t)l0 * CC + tid * 4);

    // ---- B fragments (32 regs) for this warp's l ----
    uint32_t bf[4][4][2];
    {
        const float* wp = weight + (size_t)lg * CC * CC;
        #pragma unroll
        for (int nt = 0; nt < 4; nt++)
            #pragma unroll
            for (int kt = 0; kt < 4; kt++) {
                bf[kt][nt][0] = f2tf32(__ldg(wp + (8 * kt + q) * CC + 8 * nt + p));
                bf[kt][nt][1] = f2tf32(__ldg(wp + (8 * kt + q + 4) * CC + 8 * nt + p));
            }
    }

    for (int ch = 0; ch < NCH; ch++) {
        // ---- stage prefetched chunk into x_s (conflict-free STS) ----
        #pragma unroll
        for (int it = 0; it < 4; it++) {
            int i = it * THREADS + tid;
            int s = i & 1, r = i >> 1;
            int bl = r >> 5, c = r & 31;
            // perm(c): c=8kt+4h+qq -> 8qq+2kt+h ; + row rot 4(bl&7) + seg rot 4s
            // (plane l = 4s+h -> l>>2 == s). Banks e0{8qq+m} + 4s: disjoint halves.
            int e = ((((c & 3) << 3) | ((c >> 3) << 1) | ((c >> 2) & 1))
                     + 4 * (bl & 7) + 4 * s) & 31;
            uint32_t* dst = x_s + bl * CC + e;
            float4 v = pf[it];
            dst[(4 * s + 0) * XPLANE] = f2tf32(v.x);
            dst[(4 * s + 1) * XPLANE] = f2tf32(v.y);
            dst[(4 * s + 2) * XPLANE] = f2tf32(v.z);
            dst[(4 * s + 3) * XPLANE] = f2tf32(v.w);
        }
        // ---- prefetch next chunk (latency hidden under compute + out) ----
        if (ch + 1 < NCH) {
            int cbn = b0 + (ch + 1) * BCH;
            #pragma unroll
            for (int it = 0; it < 4; it++) {
                int i = it * THREADS + tid;
                int s = i & 1, r = i >> 1;
                pf[it] = *(const float4*)(x + ((size_t)((cbn + (r >> 5)) * CC + (r & 31))) * LL + l0 + 4 * s);
            }
        }
        __syncthreads();   // x_s ready; also fences out-pass(ch-1) o_s reads

        // ---- compute: warp w -> l; 4x LDS.128 + 16 mma; bias from smem ----
        {
            const uint32_t* xp = x_s + w * XPLANE;
            const int rot = 4 * p + 4 * (w >> 2);    // row rot (p == (p+8)&7) + seg rot
            const int o1 = (8 * q + rot) & 31;       // multiple of 4, <=28: no wrap
            const int o2 = (8 * q + 4 + rot) & 31;
            uint4 v00 = *(const uint4*)(xp + p * CC + o1);
            uint4 v01 = *(const uint4*)(xp + p * CC + o2);
            uint4 v10 = *(const uint4*)(xp + (p + 8) * CC + o1);
            uint4 v11 = *(const uint4*)(xp + (p + 8) * CC + o2);

            float* op = o_s + w * OPLANE;
            const float* bp = bias_s + w * CC;
            #pragma unroll
            for (int nt = 0; nt < 4; nt++) {
                float2 bv = *(const float2*)(bp + 8 * nt + 2 * q);   // broadcast LDS.64
                float a0 = bv.x, a1 = bv.y, a2 = bv.x, a3 = bv.y;
                mma_tf32(a0, a1, a2, a3, v00.x, v10.x, v00.y, v10.y,
                         bf[0][nt][0], bf[0][nt][1], a0, a1, a2, a3);
                mma_tf32(a0, a1, a2, a3, v00.z, v10.z, v00.w, v10.w,
                         bf[1][nt][0], bf[1][nt][1], a0, a1, a2, a3);
                mma_tf32(a0, a1, a2, a3, v01.x, v11.x, v01.y, v11.y,
                         bf[2][nt][0], bf[2][nt][1], a0, a1, a2, a3);
                mma_tf32(a0, a1, a2, a3, v01.z, v11.z, v01.w, v11.w,
                         bf[3][nt][0], bf[3][nt][1], a0, a1, a2, a3);
                int d = 8 * nt + 2 * q;          // store banks 8q+p: conflict-free
                op[d * OPITCH + p]           = a0;
                op[(d + 1) * OPITCH + p]     = a1;
                op[d * OPITCH + p + 8]       = a2;
                op[(d + 1) * OPITCH + p + 8] = a3;
            }
        }
        __syncthreads();   // o_s ready

        // ---- out-pass: d fixed per warp-instr; gather banks bl+16s2(+4j) ----
        {
            const int cb = b0 + ch * BCH;
            const int bl = lane & 15, s2 = lane >> 4;
            #pragma unroll
            for (int it = 0; it < 4; it++) {
                int d = it * 8 + w;
                const float* src = o_s + (4 * s2) * OPLANE + d * OPITCH + bl;
                float4 v;
                v.x = src[0 * OPLANE];
                v.y = src[1 * OPLANE];
                v.z = src[2 * OPLANE];
                v.w = src[3 * OPLANE];
                *(float4*)(out + ((size_t)((cb + bl) * CC + d)) * LL + l0 + 4 * s2) = v;
            }
        }
        // next stage writes x_s only (disjoint from o_s); next compute's o_s
        // writes are fenced by the next stage-end sync.
    }
}

extern "C" void kernel_launch(void* const* d_in, const int* in_sizes, int n_in,
                              void* d_out, int out_size) {
    const float* x      = (const float*)d_in[0];
    // d_in[1] = px, unused by the reference
    const float* weight = (const float*)d_in[2];
    const float* bias   = (const float*)d_in[3];
    float* out          = (float*)d_out;

    dim3 grid(BSPLIT, LL / LT);   // (2, 512): weight-sharing siblings adjacent
    dim3 block(THREADS);
    dyna_dec_kernel<<<grid, block>>>(x, weight, bias, out);
}